// round 15
// baseline (speedup 1.0000x reference)
#include <cuda_runtime.h>
#include <cuda_fp16.h>
#include <cstdint>

// ---------------------------------------------------------------------------
// Problem constants
// ---------------------------------------------------------------------------
#define BATCH 8
#define CIN   32
#define HH    96
#define WW    96
#define OCN   64
#define OHW   96
#define SSZ   (OHW*OHW)      // 9216
#define KK    (CIN*3*3)      // 288

#define TILE_H 16
#define TILE_W 16
#define PATCH_H 18
#define PATCH_W 18
#define NPIX    (PATCH_H*PATCH_W)    // 324

// Dynamic smem layout (bytes) — 112.5KB; (115200+1024)*2 = 232448 <= 233472
#define SM_W      0                   // resident weights: 9*64 rows x 128B
#define SM_P      73728               // patch fp16: 324 rows x 128B = 41472
#define SM_TOTAL  115200

// Preprocessed weights: [9 tap][64 oc][64 k] fp16 (k = cin | 32+cin)
__device__ __align__(16) __half g_W[9*64*64];
__device__ float g_bias[OCN];

// ---------------------------------------------------------------------------
// Weight prep: grid(64), block(256); tree-reduced bias.
// ---------------------------------------------------------------------------
__global__ __launch_bounds__(256)
void prep_w_kernel(const float* __restrict__ pos,
                   const float* __restrict__ val) {
    __shared__ float red[256];
    const int tid = threadIdx.x;
    const int oc  = blockIdx.x;
    float part = 0.f;
    for (int k = tid; k < KK; k += 256) {
        const float* p = pos + ((size_t)(oc*KK + k))*3;
        const float* v = val + ((size_t)(oc*KK + k))*3;
        float q0 = p[0], q1 = p[1], q2 = p[2];
        float v0 = v[0], v1 = v[1], v2 = v[2];
        float dp0 = q1 - q0, dp1 = q2 - q1;
        float s0 = (dp0 > 0.f) ? (v1 - v0) / dp0 : 0.f;
        float s1 = (dp1 > 0.f) ? (v2 - v1) / dp1 : 0.f;

        int cin = k / 9;
        int tap = k - cin*9;

        size_t rb = ((size_t)tap*64 + oc)*64;
        g_W[rb + cin]      = __float2half(s0);
        g_W[rb + 32 + cin] = __float2half(s1);

        part += v0 - s0*q0 - s1*q1;
    }
    red[tid] = part;
    __syncthreads();
#pragma unroll
    for (int s = 128; s > 0; s >>= 1) {
        if (tid < s) red[tid] += red[tid + s];
        __syncthreads();
    }
    if (tid == 0) g_bias[oc] = red[0];
}

// ---------------------------------------------------------------------------
// MMA / cp.async helpers (baseline sm_80+ PTX)
// ---------------------------------------------------------------------------
__device__ __forceinline__ void ldsm4(uint32_t& r0, uint32_t& r1,
                                      uint32_t& r2, uint32_t& r3,
                                      uint32_t addr) {
    asm volatile("ldmatrix.sync.aligned.m8n8.x4.shared.b16 {%0,%1,%2,%3}, [%4];"
                 : "=r"(r0), "=r"(r1), "=r"(r2), "=r"(r3) : "r"(addr));
}
__device__ __forceinline__ void mma_f16(float* d,
                                        uint32_t a0, uint32_t a1,
                                        uint32_t a2, uint32_t a3,
                                        uint32_t b0, uint32_t b1) {
    asm volatile(
        "mma.sync.aligned.m16n8k16.row.col.f32.f16.f16.f32 "
        "{%0,%1,%2,%3}, {%4,%5,%6,%7}, {%8,%9}, {%0,%1,%2,%3};"
        : "+f"(d[0]), "+f"(d[1]), "+f"(d[2]), "+f"(d[3])
        : "r"(a0), "r"(a1), "r"(a2), "r"(a3), "r"(b0), "r"(b1));
}
__device__ __forceinline__ uint32_t smem_u32(const void* p) {
    uint32_t a;
    asm("{ .reg .u64 t; cvta.to.shared.u64 t, %1; cvt.u32.u64 %0, t; }"
        : "=r"(a) : "l"(p));
    return a;
}
__device__ __forceinline__ void cp_async16(uint32_t dst, const void* src) {
    asm volatile("cp.async.cg.shared.global [%0], [%1], 16;"
                 :: "r"(dst), "l"(src) : "memory");
}
__device__ __forceinline__ void cp_commit() {
    asm volatile("cp.async.commit_group;" ::: "memory");
}
__device__ __forceinline__ void cp_wait0() {
    asm volatile("cp.async.wait_group 0;" ::: "memory");
}
__device__ __forceinline__ uint32_t h2_as_u32(__half2 v) {
    return reinterpret_cast<const uint32_t&>(v);
}

// ---------------------------------------------------------------------------
// Main: grid(288), 512 threads, one 16x16 tile per block.
// 16 warps: warp = (whalf: oc half) x (wrow: 2 oh rows) -> 288 MMA/warp.
// 32 warps/SM (occ 50%) to hide ldsm/mma latency; weights smem-resident.
// ---------------------------------------------------------------------------
__global__ __launch_bounds__(512, 2)
void pw_mma_kernel(const float* __restrict__ x,
                   const float* __restrict__ pos,
                   float* __restrict__ out) {
    extern __shared__ char smem[];
    const uint32_t sb = smem_u32(smem);
    const int tid = threadIdx.x;
    const int l   = tid & 31;
    const int w   = tid >> 5;           // 0..15
    const int whalf = w >> 3;           // oc half (0: oc0-31, 1: oc32-63)
    const int wrow  = w & 7;            // 2 oh rows {2*wrow, 2*wrow+1}

    // lane constants (validated choreography)
    const int rA     = l & 15;
    const int khalfA = l >> 4;
    const int ocb    = ((l >> 4) & 1)*8 + (l & 7);
    const int khalfB = (l >> 3) & 1;
    const int bsw    = l & 7;

    const int tile = blockIdx.x;               // 0..287
    const int bb   = tile / 36;                // batch 0..7
    const int rem  = tile - bb*36;
    const int oh0  = (rem / 6) * TILE_H;
    const int ow0  = (rem - (rem/6)*6) * TILE_W;

    const float P0f = pos[0], P1f = pos[1], P2f = pos[2];
    const __half2 P0 = __float2half2_rn(P0f);
    const __half2 P1 = __float2half2_rn(P1f);
    const __half2 P2 = __float2half2_rn(P2f);

    // ---- stage ALL weights (cp.async, swizzled) — overlaps patch work ----
    {
        const char* gw = (const char*)g_W;
        for (int idx = tid; idx < 4608; idx += 512) {  // 576 rows x 8 chunks
            int row = idx >> 3, c = idx & 7;
            cp_async16(sb + SM_W + row*128 + ((c ^ (row & 7)) << 4),
                       gw + row*128 + c*16);
        }
        cp_commit();
    }

    // ---- in-kernel patch staging: each thread owns <=1 pixel ----
    if (tid < NPIX) {
        const float* xb = x + (size_t)bb * (CIN*HH*WW);
        int p  = tid;
        int ph = p / PATCH_W, pw = p - ph*PATCH_W;
        int h  = oh0 - 1 + ph, w2 = ow0 - 1 + pw;
        int inb = ((unsigned)h < HH) && ((unsigned)w2 < WW);
        int off = inb ? h*WW + w2 : 0;
#pragma unroll
        for (int jb = 0; jb < 4; jb++) {        // 8 channels per iteration
            uint32_t qa[4], qb[4];
#pragma unroll
            for (int q = 0; q < 4; q++) {
                int ch = jb*8 + 2*q;
                float x0 = inb ? xb[(size_t)ch*HH*WW + off] : 0.f;
                float x1 = inb ? xb[(size_t)(ch+1)*HH*WW + off] : 0.f;
                __half2 hv = __floats2half2_rn(x0, x1);
                qa[q] = h2_as_u32(__hmin2(__hmax2(hv, P0), P1));
                qb[q] = h2_as_u32(__hmin2(__hmax2(hv, P1), P2));
            }
            int c0 = jb, c1 = jb + 4;
            *(uint4*)(smem + SM_P + p*128 + ((c0 ^ (p & 7)) << 4)) =
                make_uint4(qa[0], qa[1], qa[2], qa[3]);
            *(uint4*)(smem + SM_P + p*128 + ((c1 ^ (p & 7)) << 4)) =
                make_uint4(qb[0], qb[1], qb[2], qb[3]);
        }
    }

    // hoist bias loads: latency hides under the MMA loop
    float bias0[4], bias1[4];
    {
        int cp = (l & 3) * 2;
#pragma unroll
        for (int nt = 0; nt < 4; nt++) {
            int oc = whalf*32 + nt*8 + cp;
            bias0[nt] = __ldg(&g_bias[oc]);
            bias1[nt] = __ldg(&g_bias[oc + 1]);
        }
    }

    cp_wait0();
    __syncthreads();

    // ---- HMMA: kw-outer, A fragments shared across kh ----
    float acc[2][4][4];                 // [row r][nt][frag]
#pragma unroll
    for (int r = 0; r < 2; r++)
#pragma unroll
        for (int nt = 0; nt < 4; nt++)
#pragma unroll
            for (int i = 0; i < 4; i++) acc[r][nt][i] = 0.f;

#pragma unroll
    for (int kw = 0; kw < 3; kw++) {
#pragma unroll
        for (int ks = 0; ks < 4; ks++) {
            // 4 A fragments: i = r + kh in [0,3]
            int kcA = ks*2 + khalfA;
            uint32_t af[4][4];
#pragma unroll
            for (int i = 0; i < 4; i++) {
                int pix = (2*wrow + i)*PATCH_W + rA + kw;
                uint32_t aaddr = sb + SM_P + pix*128
                               + ((kcA ^ (pix & 7)) << 4);
                ldsm4(af[i][0], af[i][1], af[i][2], af[i][3], aaddr);
            }
            int kcB = ks*2 + khalfB;
#pragma unroll
            for (int kh = 0; kh < 3; kh++) {
                int tap = kh*3 + kw;
                uint32_t boff = sb + SM_W + tap*8192
                              + (whalf*32 + ocb)*128;
                uint32_t bf[8];
#pragma unroll
                for (int i = 0; i < 2; i++) {   // 32 oc = 2 x 16-row blocks
                    uint32_t baddr = boff + i*2048 + ((kcB ^ bsw) << 4);
                    ldsm4(bf[4*i+0], bf[4*i+1], bf[4*i+2], bf[4*i+3], baddr);
                }
#pragma unroll
                for (int r = 0; r < 2; r++) {
                    const uint32_t* a = af[r + kh];
#pragma unroll
                    for (int nt = 0; nt < 4; nt++)
                        mma_f16(acc[r][nt], a[0], a[1], a[2], a[3],
                                bf[2*nt], bf[2*nt+1]);
                }
            }
        }
    }

    // ---- epilogue ----
    {
        int r0 = l >> 2;
#pragma unroll
        for (int r = 0; r < 2; r++) {
            int oh = oh0 + 2*wrow + r;
            size_t pbase = (size_t)bb*OCN*SSZ + (size_t)oh*OHW + ow0;
#pragma unroll
            for (int nt = 0; nt < 4; nt++) {
                int oc = whalf*32 + nt*8 + (l & 3)*2;
                float* o0 = out + pbase + (size_t)oc*SSZ;
                float* o1 = o0 + SSZ;
                o0[r0]     = acc[r][nt][0] + bias0[nt];
                o1[r0]     = acc[r][nt][1] + bias1[nt];
                o0[r0 + 8] = acc[r][nt][2] + bias0[nt];
                o1[r0 + 8] = acc[r][nt][3] + bias1[nt];
            }
        }
    }
}

// ---------------------------------------------------------------------------
extern "C" void kernel_launch(void* const* d_in, const int* in_sizes, int n_in,
                              void* d_out, int out_size) {
    const float* x   = (const float*)d_in[0];  // [8,32,96,96]
    const float* pos = (const float*)d_in[1];  // [64,32,3,3,3]
    const float* val = (const float*)d_in[2];  // [64,32,3,3,3]
    float* out = (float*)d_out;                // [8,64,96,96]

    cudaFuncSetAttribute(pw_mma_kernel,
                         cudaFuncAttributeMaxDynamicSharedMemorySize,
                         SM_TOTAL);

    prep_w_kernel<<<OCN, 256>>>(pos, val);
    pw_mma_kernel<<<288, 512, SM_TOTAL>>>(x, pos, out);
}

// round 16
// speedup vs baseline: 1.0770x; 1.0770x over previous
#include <cuda_runtime.h>
#include <cuda_fp16.h>
#include <cstdint>

// ---------------------------------------------------------------------------
// Problem constants
// ---------------------------------------------------------------------------
#define BATCH 8
#define CIN   32
#define HH    96
#define WW    96
#define OCN   64
#define OHW   96
#define SSZ   (OHW*OHW)      // 9216
#define KK    (CIN*3*3)      // 288

#define TILE_H 16
#define TILE_W 16
#define PATCH_H 18
#define PATCH_W 18
#define NPIX    (PATCH_H*PATCH_W)    // 324

// Dynamic smem layout (bytes) — 112.5KB; (115200+1024)*2 = 232448 <= 233472
#define SM_W      0                   // resident weights: 9*64 rows x 128B
#define SM_P      73728               // patch fp16: 324 rows x 128B = 41472
#define SM_TOTAL  115200

// Preprocessed weights: [9 tap][64 oc][64 k] fp16 (k = cin | 32+cin)
__device__ __align__(16) __half g_W[9*64*64];
__device__ float g_bias[OCN];

// ---------------------------------------------------------------------------
// Weight prep: grid(64), block(256); tree-reduced bias.
// ---------------------------------------------------------------------------
__global__ __launch_bounds__(256)
void prep_w_kernel(const float* __restrict__ pos,
                   const float* __restrict__ val) {
    __shared__ float red[256];
    const int tid = threadIdx.x;
    const int oc  = blockIdx.x;
    float part = 0.f;
    for (int k = tid; k < KK; k += 256) {
        const float* p = pos + ((size_t)(oc*KK + k))*3;
        const float* v = val + ((size_t)(oc*KK + k))*3;
        float q0 = p[0], q1 = p[1], q2 = p[2];
        float v0 = v[0], v1 = v[1], v2 = v[2];
        float dp0 = q1 - q0, dp1 = q2 - q1;
        float s0 = (dp0 > 0.f) ? (v1 - v0) / dp0 : 0.f;
        float s1 = (dp1 > 0.f) ? (v2 - v1) / dp1 : 0.f;

        int cin = k / 9;
        int tap = k - cin*9;

        size_t rb = ((size_t)tap*64 + oc)*64;
        g_W[rb + cin]      = __float2half(s0);
        g_W[rb + 32 + cin] = __float2half(s1);

        part += v0 - s0*q0 - s1*q1;
    }
    red[tid] = part;
    __syncthreads();
#pragma unroll
    for (int s = 128; s > 0; s >>= 1) {
        if (tid < s) red[tid] += red[tid + s];
        __syncthreads();
    }
    if (tid == 0) g_bias[oc] = red[0];
}

// ---------------------------------------------------------------------------
// MMA / cp.async helpers (baseline sm_80+ PTX)
// ---------------------------------------------------------------------------
__device__ __forceinline__ void ldsm4(uint32_t& r0, uint32_t& r1,
                                      uint32_t& r2, uint32_t& r3,
                                      uint32_t addr) {
    asm volatile("ldmatrix.sync.aligned.m8n8.x4.shared.b16 {%0,%1,%2,%3}, [%4];"
                 : "=r"(r0), "=r"(r1), "=r"(r2), "=r"(r3) : "r"(addr));
}
__device__ __forceinline__ void mma_f16(float* d,
                                        uint32_t a0, uint32_t a1,
                                        uint32_t a2, uint32_t a3,
                                        uint32_t b0, uint32_t b1) {
    asm volatile(
        "mma.sync.aligned.m16n8k16.row.col.f32.f16.f16.f32 "
        "{%0,%1,%2,%3}, {%4,%5,%6,%7}, {%8,%9}, {%0,%1,%2,%3};"
        : "+f"(d[0]), "+f"(d[1]), "+f"(d[2]), "+f"(d[3])
        : "r"(a0), "r"(a1), "r"(a2), "r"(a3), "r"(b0), "r"(b1));
}
__device__ __forceinline__ uint32_t smem_u32(const void* p) {
    uint32_t a;
    asm("{ .reg .u64 t; cvta.to.shared.u64 t, %1; cvt.u32.u64 %0, t; }"
        : "=r"(a) : "l"(p));
    return a;
}
__device__ __forceinline__ void cp_async16(uint32_t dst, const void* src) {
    asm volatile("cp.async.cg.shared.global [%0], [%1], 16;"
                 :: "r"(dst), "l"(src) : "memory");
}
__device__ __forceinline__ void cp_commit() {
    asm volatile("cp.async.commit_group;" ::: "memory");
}
__device__ __forceinline__ void cp_wait0() {
    asm volatile("cp.async.wait_group 0;" ::: "memory");
}
__device__ __forceinline__ uint32_t h2_as_u32(__half2 v) {
    return reinterpret_cast<const uint32_t&>(v);
}

// ---------------------------------------------------------------------------
// Main: grid(288), 256 threads, one 16x16 tile per block.
// Per (kw,ks): issue ALL 12 ldsm (6 A + 6 B covering 3 kh taps) back-to-back,
// then run 24 dependency-free MMAs from registers — one latency exposure per
// 24 MMAs instead of one per 8.
// ---------------------------------------------------------------------------
__global__ __launch_bounds__(256, 2)
void pw_mma_kernel(const float* __restrict__ x,
                   const float* __restrict__ pos,
                   float* __restrict__ out) {
    extern __shared__ char smem[];
    const uint32_t sb = smem_u32(smem);
    const int tid = threadIdx.x;
    const int l   = tid & 31;
    const int w   = tid >> 5;
    const int whalf = w >> 2;           // oc half (0: oc0-31, 1: oc32-63)
    const int wrow  = w & 3;            // 4 oh rows {4*wrow .. 4*wrow+3}

    // lane constants (validated choreography)
    const int rA     = l & 15;
    const int khalfA = l >> 4;
    const int ocb    = ((l >> 4) & 1)*8 + (l & 7);
    const int khalfB = (l >> 3) & 1;
    const int bsw    = l & 7;

    const int tile = blockIdx.x;               // 0..287
    const int bb   = tile / 36;                // batch 0..7
    const int rem  = tile - bb*36;
    const int oh0  = (rem / 6) * TILE_H;
    const int ow0  = (rem - (rem/6)*6) * TILE_W;

    const float P0f = pos[0], P1f = pos[1], P2f = pos[2];
    const __half2 P0 = __float2half2_rn(P0f);
    const __half2 P1 = __float2half2_rn(P1f);
    const __half2 P2 = __float2half2_rn(P2f);

    // ---- stage ALL weights (cp.async, swizzled) — overlaps patch work ----
    {
        const char* gw = (const char*)g_W;
        for (int idx = tid; idx < 4608; idx += 256) {  // 576 rows x 8 chunks
            int row = idx >> 3, c = idx & 7;
            cp_async16(sb + SM_W + row*128 + ((c ^ (row & 7)) << 4),
                       gw + row*128 + c*16);
        }
        cp_commit();
    }

    // ---- in-kernel patch staging: fp32 x -> clamped fp16, swizzled ----
    {
        const float* xb = x + (size_t)bb * (CIN*HH*WW);
        int offp[2]; int inbp[2];
#pragma unroll
        for (int s = 0; s < 2; s++) {
            int p  = tid + s*256;
            int ph = p / PATCH_W;
            int pw = p - ph*PATCH_W;
            int h  = oh0 - 1 + ph;
            int w2 = ow0 - 1 + pw;
            inbp[s] = (p < NPIX) && ((unsigned)h < HH) && ((unsigned)w2 < WW);
            offp[s] = (inbp[s] ? h*WW + w2 : 0);
        }
#pragma unroll
        for (int jb = 0; jb < 4; jb++) {        // 8 channels per block
#pragma unroll
            for (int s = 0; s < 2; s++) {
                int p = tid + s*256;
                if (p >= NPIX) break;
                uint32_t qa[4], qb[4];
#pragma unroll
                for (int q = 0; q < 4; q++) {
                    int ch = jb*8 + 2*q;
                    float x0 = inbp[s] ? xb[(size_t)ch*HH*WW + offp[s]] : 0.f;
                    float x1 = inbp[s] ? xb[(size_t)(ch+1)*HH*WW + offp[s]]
                                       : 0.f;
                    __half2 hv = __floats2half2_rn(x0, x1);
                    qa[q] = h2_as_u32(__hmin2(__hmax2(hv, P0), P1));
                    qb[q] = h2_as_u32(__hmin2(__hmax2(hv, P1), P2));
                }
                int c0 = jb, c1 = jb + 4;
                *(uint4*)(smem + SM_P + p*128 + ((c0 ^ (p & 7)) << 4)) =
                    make_uint4(qa[0], qa[1], qa[2], qa[3]);
                *(uint4*)(smem + SM_P + p*128 + ((c1 ^ (p & 7)) << 4)) =
                    make_uint4(qb[0], qb[1], qb[2], qb[3]);
            }
        }
    }

    // hoist bias loads: latency hides under the MMA loop
    float bias0[4], bias1[4];
    {
        int cp = (l & 3) * 2;
#pragma unroll
        for (int nt = 0; nt < 4; nt++) {
            int oc = whalf*32 + nt*8 + cp;
            bias0[nt] = __ldg(&g_bias[oc]);
            bias1[nt] = __ldg(&g_bias[oc + 1]);
        }
    }

    cp_wait0();
    __syncthreads();

    // ---- HMMA: kw-outer; per (kw,ks) all 12 ldsm first, then 24 MMAs ----
    float acc[4][4][4];                 // [row r][nt][frag]
#pragma unroll
    for (int r = 0; r < 4; r++)
#pragma unroll
        for (int nt = 0; nt < 4; nt++)
#pragma unroll
            for (int i = 0; i < 4; i++) acc[r][nt][i] = 0.f;

#pragma unroll
    for (int kw = 0; kw < 3; kw++) {
#pragma unroll
        for (int ks = 0; ks < 4; ks++) {
            int kcA = ks*2 + khalfA;
            int kcB = ks*2 + khalfB;

            // 6 A fragments: i = r + kh in [0,5]
            uint32_t af[6][4];
#pragma unroll
            for (int i = 0; i < 6; i++) {
                int pix = (4*wrow + i)*PATCH_W + rA + kw;
                uint32_t aaddr = sb + SM_P + pix*128
                               + ((kcA ^ (pix & 7)) << 4);
                ldsm4(af[i][0], af[i][1], af[i][2], af[i][3], aaddr);
            }
            // 6 B fragment-halves: all 3 kh taps up front
            uint32_t bf[3][8];
#pragma unroll
            for (int kh = 0; kh < 3; kh++) {
                int tap = kh*3 + kw;
                uint32_t boff = sb + SM_W + tap*8192
                              + (whalf*32 + ocb)*128;
#pragma unroll
                for (int i = 0; i < 2; i++) {   // 32 oc = 2 x 16-row blocks
                    uint32_t baddr = boff + i*2048 + ((kcB ^ bsw) << 4);
                    ldsm4(bf[kh][4*i+0], bf[kh][4*i+1],
                          bf[kh][4*i+2], bf[kh][4*i+3], baddr);
                }
            }
            // 24 dependency-free MMAs from registers
#pragma unroll
            for (int kh = 0; kh < 3; kh++) {
#pragma unroll
                for (int r = 0; r < 4; r++) {
                    const uint32_t* a = af[r + kh];
#pragma unroll
                    for (int nt = 0; nt < 4; nt++)
                        mma_f16(acc[r][nt], a[0], a[1], a[2], a[3],
                                bf[kh][2*nt], bf[kh][2*nt+1]);
                }
            }
        }
    }

    // ---- epilogue ----
    {
        int r0 = l >> 2;
#pragma unroll
        for (int r = 0; r < 4; r++) {
            int oh = oh0 + 4*wrow + r;
            size_t pbase = (size_t)bb*OCN*SSZ + (size_t)oh*OHW + ow0;
#pragma unroll
            for (int nt = 0; nt < 4; nt++) {
                int oc = whalf*32 + nt*8 + (l & 3)*2;
                float* o0 = out + pbase + (size_t)oc*SSZ;
                float* o1 = o0 + SSZ;
                o0[r0]     = acc[r][nt][0] + bias0[nt];
                o1[r0]     = acc[r][nt][1] + bias1[nt];
                o0[r0 + 8] = acc[r][nt][2] + bias0[nt];
                o1[r0 + 8] = acc[r][nt][3] + bias1[nt];
            }
        }
    }
}

// ---------------------------------------------------------------------------
extern "C" void kernel_launch(void* const* d_in, const int* in_sizes, int n_in,
                              void* d_out, int out_size) {
    const float* x   = (const float*)d_in[0];  // [8,32,96,96]
    const float* pos = (const float*)d_in[1];  // [64,32,3,3,3]
    const float* val = (const float*)d_in[2];  // [64,32,3,3,3]
    float* out = (float*)d_out;                // [8,64,96,96]

    cudaFuncSetAttribute(pw_mma_kernel,
                         cudaFuncAttributeMaxDynamicSharedMemorySize,
                         SM_TOTAL);

    prep_w_kernel<<<OCN, 256>>>(pos, val);
    pw_mma_kernel<<<288, 256, SM_TOTAL>>>(x, pos, out);
}

// round 17
// speedup vs baseline: 1.0875x; 1.0097x over previous
#include <cuda_runtime.h>
#include <cuda_fp16.h>
#include <cstdint>

// ---------------------------------------------------------------------------
// Problem constants
// ---------------------------------------------------------------------------
#define BATCH 8
#define CIN   32
#define HH    96
#define WW    96
#define OCN   64
#define OHW   96
#define SSZ   (OHW*OHW)      // 9216
#define KK    (CIN*3*3)      // 288

#define TILE_H 16
#define TILE_W 16
#define PATCH_H 18
#define PATCH_W 18
#define NPIX    (PATCH_H*PATCH_W)    // 324

// Dynamic smem layout (bytes) — 112.5KB; (115200+1024)*2 = 232448 <= 233472
#define SM_W      0                   // resident weights: 9*64 rows x 128B
#define SM_P      73728               // patch fp16: 324 rows x 128B = 41472
#define SM_TOTAL  115200

// Preprocessed weights: [9 tap][64 oc][64 k] fp16 (k = cin | 32+cin)
__device__ __align__(16) __half g_W[9*64*64];
__device__ float g_bias[OCN];

// ---------------------------------------------------------------------------
// Weight prep: grid(64), block(256); tree-reduced bias.
// ---------------------------------------------------------------------------
__global__ __launch_bounds__(256)
void prep_w_kernel(const float* __restrict__ pos,
                   const float* __restrict__ val) {
    __shared__ float red[256];
    const int tid = threadIdx.x;
    const int oc  = blockIdx.x;
    float part = 0.f;
    for (int k = tid; k < KK; k += 256) {
        const float* p = pos + ((size_t)(oc*KK + k))*3;
        const float* v = val + ((size_t)(oc*KK + k))*3;
        float q0 = p[0], q1 = p[1], q2 = p[2];
        float v0 = v[0], v1 = v[1], v2 = v[2];
        float dp0 = q1 - q0, dp1 = q2 - q1;
        float s0 = (dp0 > 0.f) ? (v1 - v0) / dp0 : 0.f;
        float s1 = (dp1 > 0.f) ? (v2 - v1) / dp1 : 0.f;

        int cin = k / 9;
        int tap = k - cin*9;

        size_t rb = ((size_t)tap*64 + oc)*64;
        g_W[rb + cin]      = __float2half(s0);
        g_W[rb + 32 + cin] = __float2half(s1);

        part += v0 - s0*q0 - s1*q1;
    }
    red[tid] = part;
    __syncthreads();
#pragma unroll
    for (int s = 128; s > 0; s >>= 1) {
        if (tid < s) red[tid] += red[tid + s];
        __syncthreads();
    }
    if (tid == 0) g_bias[oc] = red[0];
}

// ---------------------------------------------------------------------------
// MMA / cp.async helpers (baseline sm_80+ PTX)
// ---------------------------------------------------------------------------
__device__ __forceinline__ void ldsm4(uint32_t& r0, uint32_t& r1,
                                      uint32_t& r2, uint32_t& r3,
                                      uint32_t addr) {
    asm volatile("ldmatrix.sync.aligned.m8n8.x4.shared.b16 {%0,%1,%2,%3}, [%4];"
                 : "=r"(r0), "=r"(r1), "=r"(r2), "=r"(r3) : "r"(addr));
}
__device__ __forceinline__ void mma_f16(float* d,
                                        uint32_t a0, uint32_t a1,
                                        uint32_t a2, uint32_t a3,
                                        uint32_t b0, uint32_t b1) {
    asm volatile(
        "mma.sync.aligned.m16n8k16.row.col.f32.f16.f16.f32 "
        "{%0,%1,%2,%3}, {%4,%5,%6,%7}, {%8,%9}, {%0,%1,%2,%3};"
        : "+f"(d[0]), "+f"(d[1]), "+f"(d[2]), "+f"(d[3])
        : "r"(a0), "r"(a1), "r"(a2), "r"(a3), "r"(b0), "r"(b1));
}
__device__ __forceinline__ uint32_t smem_u32(const void* p) {
    uint32_t a;
    asm("{ .reg .u64 t; cvta.to.shared.u64 t, %1; cvt.u32.u64 %0, t; }"
        : "=r"(a) : "l"(p));
    return a;
}
__device__ __forceinline__ void cp_async16(uint32_t dst, const void* src) {
    asm volatile("cp.async.cg.shared.global [%0], [%1], 16;"
                 :: "r"(dst), "l"(src) : "memory");
}
__device__ __forceinline__ void cp_commit() {
    asm volatile("cp.async.commit_group;" ::: "memory");
}
__device__ __forceinline__ void cp_wait0() {
    asm volatile("cp.async.wait_group 0;" ::: "memory");
}
__device__ __forceinline__ uint32_t h2_as_u32(__half2 v) {
    return reinterpret_cast<const uint32_t&>(v);
}

// ---------------------------------------------------------------------------
// Main: grid(288), 256 threads, one 16x16 tile per block.
// Warp-rotated kw/ks iteration order to decorrelate tensor-pipe bubbles;
// CTA-staggered staging order to spread the L2 storm.
// ---------------------------------------------------------------------------
__global__ __launch_bounds__(256, 2)
void pw_mma_kernel(const float* __restrict__ x,
                   const float* __restrict__ pos,
                   float* __restrict__ out) {
    extern __shared__ char smem[];
    const uint32_t sb = smem_u32(smem);
    const int tid = threadIdx.x;
    const int l   = tid & 31;
    const int w   = tid >> 5;
    const int whalf = w >> 2;           // oc half (0: oc0-31, 1: oc32-63)
    const int wrow  = w & 3;            // 4 oh rows {4*wrow .. 4*wrow+3}

    // lane constants (validated choreography)
    const int rA     = l & 15;
    const int khalfA = l >> 4;
    const int ocb    = ((l >> 4) & 1)*8 + (l & 7);
    const int khalfB = (l >> 3) & 1;
    const int bsw    = l & 7;

    const int tile = blockIdx.x;               // 0..287
    const int bb   = tile / 36;                // batch 0..7
    const int rem  = tile - bb*36;
    const int oh0  = (rem / 6) * TILE_H;
    const int ow0  = (rem - (rem/6)*6) * TILE_W;

    const float P0f = pos[0], P1f = pos[1], P2f = pos[2];
    const __half2 P0 = __float2half2_rn(P0f);
    const __half2 P1 = __float2half2_rn(P1f);
    const __half2 P2 = __float2half2_rn(P2f);

    // ---- stage ALL weights (cp.async, swizzled); CTA-staggered start ----
    {
        const char* gw = (const char*)g_W;
        const int start = (blockIdx.x & 1) ? 2304 : 0;
        for (int ii = tid; ii < 4608; ii += 256) {
            int idx = ii + start; if (idx >= 4608) idx -= 4608;
            int row = idx >> 3, c = idx & 7;
            cp_async16(sb + SM_W + row*128 + ((c ^ (row & 7)) << 4),
                       gw + row*128 + c*16);
        }
        cp_commit();
    }

    // ---- in-kernel patch staging: fp32 x -> clamped fp16, swizzled ----
    {
        const float* xb = x + (size_t)bb * (CIN*HH*WW);
        int offp[2]; int inbp[2];
#pragma unroll
        for (int s = 0; s < 2; s++) {
            int p  = tid + s*256;
            int ph = p / PATCH_W;
            int pw = p - ph*PATCH_W;
            int h  = oh0 - 1 + ph;
            int w2 = ow0 - 1 + pw;
            inbp[s] = (p < NPIX) && ((unsigned)h < HH) && ((unsigned)w2 < WW);
            offp[s] = (inbp[s] ? h*WW + w2 : 0);
        }
        const int jrot = (blockIdx.x & 1) ? 2 : 0;   // CTA stagger
#pragma unroll
        for (int jj = 0; jj < 4; jj++) {        // 8 channels per block
            int jb = (jj + jrot) & 3;
#pragma unroll
            for (int s = 0; s < 2; s++) {
                int p = tid + s*256;
                if (p >= NPIX) break;
                uint32_t qa[4], qb[4];
#pragma unroll
                for (int q = 0; q < 4; q++) {
                    int ch = jb*8 + 2*q;
                    float x0 = inbp[s] ? xb[(size_t)ch*HH*WW + offp[s]] : 0.f;
                    float x1 = inbp[s] ? xb[(size_t)(ch+1)*HH*WW + offp[s]]
                                       : 0.f;
                    __half2 hv = __floats2half2_rn(x0, x1);
                    qa[q] = h2_as_u32(__hmin2(__hmax2(hv, P0), P1));
                    qb[q] = h2_as_u32(__hmin2(__hmax2(hv, P1), P2));
                }
                int c0 = jb, c1 = jb + 4;
                *(uint4*)(smem + SM_P + p*128 + ((c0 ^ (p & 7)) << 4)) =
                    make_uint4(qa[0], qa[1], qa[2], qa[3]);
                *(uint4*)(smem + SM_P + p*128 + ((c1 ^ (p & 7)) << 4)) =
                    make_uint4(qb[0], qb[1], qb[2], qb[3]);
            }
        }
    }

    // hoist bias loads: latency hides under the MMA loop
    float bias0[4], bias1[4];
    {
        int cp = (l & 3) * 2;
#pragma unroll
        for (int nt = 0; nt < 4; nt++) {
            int oc = whalf*32 + nt*8 + cp;
            bias0[nt] = __ldg(&g_bias[oc]);
            bias1[nt] = __ldg(&g_bias[oc + 1]);
        }
    }

    cp_wait0();
    __syncthreads();

    // ---- HMMA: warp-rotated (kw,ks) order; per (kw,ks) 12 ldsm then 48 MMA
    float acc[4][4][4];                 // [row r][nt][frag]
#pragma unroll
    for (int r = 0; r < 4; r++)
#pragma unroll
        for (int nt = 0; nt < 4; nt++)
#pragma unroll
            for (int i = 0; i < 4; i++) acc[r][nt][i] = 0.f;

    // warp-specific rotation offsets (decorrelate the 8 warps' phases)
    const int kwoff = w % 3;
    const int ksoff = w & 3;

#pragma unroll
    for (int kwi = 0; kwi < 3; kwi++) {
        int kw = kwi + kwoff; if (kw >= 3) kw -= 3;
#pragma unroll
        for (int ksi = 0; ksi < 4; ksi++) {
            int ks = ksi + ksoff; if (ks >= 4) ks -= 4;
            int kcA = ks*2 + khalfA;
            int kcB = ks*2 + khalfB;

            // 6 A fragments: i = r + kh in [0,5]
            uint32_t af[6][4];
#pragma unroll
            for (int i = 0; i < 6; i++) {
                int pix = (4*wrow + i)*PATCH_W + rA + kw;
                uint32_t aaddr = sb + SM_P + pix*128
                               + ((kcA ^ (pix & 7)) << 4);
                ldsm4(af[i][0], af[i][1], af[i][2], af[i][3], aaddr);
            }
            // 6 B fragment-halves: all 3 kh taps up front
            uint32_t bf[3][8];
#pragma unroll
            for (int kh = 0; kh < 3; kh++) {
                int tap = kh*3 + kw;
                uint32_t boff = sb + SM_W + tap*8192
                              + (whalf*32 + ocb)*128;
#pragma unroll
                for (int i = 0; i < 2; i++) {   // 32 oc = 2 x 16-row blocks
                    uint32_t baddr = boff + i*2048 + ((kcB ^ bsw) << 4);
                    ldsm4(bf[kh][4*i+0], bf[kh][4*i+1],
                          bf[kh][4*i+2], bf[kh][4*i+3], baddr);
                }
            }
            // 48 dependency-free MMAs from registers
#pragma unroll
            for (int kh = 0; kh < 3; kh++) {
#pragma unroll
                for (int r = 0; r < 4; r++) {
                    const uint32_t* a = af[r + kh];
#pragma unroll
                    for (int nt = 0; nt < 4; nt++)
                        mma_f16(acc[r][nt], a[0], a[1], a[2], a[3],
                                bf[kh][2*nt], bf[kh][2*nt+1]);
                }
            }
        }
    }

    // ---- epilogue ----
    {
        int r0 = l >> 2;
#pragma unroll
        for (int r = 0; r < 4; r++) {
            int oh = oh0 + 4*wrow + r;
            size_t pbase = (size_t)bb*OCN*SSZ + (size_t)oh*OHW + ow0;
#pragma unroll
            for (int nt = 0; nt < 4; nt++) {
                int oc = whalf*32 + nt*8 + (l & 3)*2;
                float* o0 = out + pbase + (size_t)oc*SSZ;
                float* o1 = o0 + SSZ;
                o0[r0]     = acc[r][nt][0] + bias0[nt];
                o1[r0]     = acc[r][nt][1] + bias1[nt];
                o0[r0 + 8] = acc[r][nt][2] + bias0[nt];
                o1[r0 + 8] = acc[r][nt][3] + bias1[nt];
            }
        }
    }
}

// ---------------------------------------------------------------------------
extern "C" void kernel_launch(void* const* d_in, const int* in_sizes, int n_in,
                              void* d_out, int out_size) {
    const float* x   = (const float*)d_in[0];  // [8,32,96,96]
    const float* pos = (const float*)d_in[1];  // [64,32,3,3,3]
    const float* val = (const float*)d_in[2];  // [64,32,3,3,3]
    float* out = (float*)d_out;                // [8,64,96,96]

    cudaFuncSetAttribute(pw_mma_kernel,
                         cudaFuncAttributeMaxDynamicSharedMemorySize,
                         SM_TOTAL);

    prep_w_kernel<<<OCN, 256>>>(pos, val);
    pw_mma_kernel<<<288, 256, SM_TOTAL>>>(x, pos, out);
}